// round 8
// baseline (speedup 1.0000x reference)
#include <cuda_runtime.h>
#include <cuda_fp16.h>
#include <cstdint>

// ---------------------------------------------------------------------------
// Problem constants
// ---------------------------------------------------------------------------
#define Bc    4
#define Cc    256
#define Hc    56
#define Wc    56
#define Gc    16
#define Kc    7
#define TNUM  256
#define HW    (Hc * Wc)          // 3136
#define CG    (Cc / Gc)          // 16
#define KK    (Kc * Kc)          // 49
#define GK    (Gc * KK)          // 784
#define EPSc  1e-5f
#define KDIM  256

// ---------------------------------------------------------------------------
// Scratch (no runtime allocation allowed)
// ---------------------------------------------------------------------------
__device__ __half g_xh[Bc * Cc * HW];
__device__ __half g_xl[Bc * Cc * HW];
__device__ __half g_th[Bc * TNUM * HW];
__device__ __half g_tl[Bc * TNUM * HW];
__device__ __half g_w1h[TNUM * Cc];
__device__ __half g_w1l[TNUM * Cc];
__device__ __half g_w2h[GK * KDIM];
__device__ __half g_w2l[GK * KDIM];
__device__ float  g_ker[Bc * GK * HW];

// ---------------------------------------------------------------------------
// helpers
// ---------------------------------------------------------------------------
__device__ __forceinline__ void split2(float x, float y,
                                       uint32_t& hi, uint32_t& lo) {
    __half hx = __float2half_rn(x);
    __half hy = __float2half_rn(y);
    __half lx = __float2half_rn(x - __half2float(hx));
    __half ly = __float2half_rn(y - __half2float(hy));
    hi = (uint32_t)__half_as_ushort(hx) | ((uint32_t)__half_as_ushort(hy) << 16);
    lo = (uint32_t)__half_as_ushort(lx) | ((uint32_t)__half_as_ushort(ly) << 16);
}

__device__ __forceinline__ uint32_t smem_u32(const void* p) {
    uint32_t a;
    asm("{ .reg .u64 t; cvta.to.shared.u64 t, %1; cvt.u32.u64 %0, t; }"
        : "=r"(a) : "l"(p));
    return a;
}

#define MMA16816(Cr, Ar, B0, B1)                                           \
    asm volatile(                                                          \
        "mma.sync.aligned.m16n8k16.row.col.f32.f16.f16.f32 "              \
        "{%0,%1,%2,%3}, {%4,%5,%6,%7}, {%8,%9}, {%0,%1,%2,%3};"           \
        : "+f"((Cr)[0]), "+f"((Cr)[1]), "+f"((Cr)[2]), "+f"((Cr)[3])       \
        : "r"((Ar)[0]), "r"((Ar)[1]), "r"((Ar)[2]), "r"((Ar)[3]),          \
          "r"(B0), "r"(B1))

#define LDSM4T(R, addr)                                                    \
    asm volatile("ldmatrix.sync.aligned.m8n8.x4.trans.shared.b16 "         \
        "{%0,%1,%2,%3}, [%4];"                                             \
        : "=r"((R)[0]), "=r"((R)[1]), "=r"((R)[2]), "=r"((R)[3])           \
        : "r"(addr))

#define CP_ASYNC16(dst, src, sz)                                           \
    asm volatile("cp.async.cg.shared.global [%0], [%1], 16, %2;"           \
        :: "r"(dst), "l"(src), "r"(sz))
#define CP_COMMIT() asm volatile("cp.async.commit_group;")

// ---------------------------------------------------------------------------
// fp32 -> fp16 hi/lo split (elementwise, float4-vectorized)
// ---------------------------------------------------------------------------
__global__ __launch_bounds__(256)
void split_kernel(const float4* __restrict__ src,
                  uint2* __restrict__ hi, uint2* __restrict__ lo, int n4)
{
    int i = blockIdx.x * blockDim.x + threadIdx.x;
    if (i >= n4) return;
    float4 v = src[i];
    uint32_t h0, l0, h1, l1;
    split2(v.x, v.y, h0, l0);
    split2(v.z, v.w, h1, l1);
    hi[i] = make_uint2(h0, h1);
    lo[i] = make_uint2(l0, l1);
}

// ---------------------------------------------------------------------------
// Split-fp16 HMMA GEMM. A fragments loaded DIRECTLY from global (weights are
// small, every CTA reads the same tile -> L2-resident), B via cp.async+ldmatrix.
//   D[M,N] = A[M,K]*B[K,N], K=256.  3 MMAs per k-step (hh+hl+lh).
// Block: 256 thr (8 warps, 4Mx2N), tile 128x64, BK=32, 3-stage B ring (27.6 KB).
// ---------------------------------------------------------------------------
#define BMg 128
#define BNg 64
#define BKg 32
#define NCH (KDIM / BKg)          // 8
#define NST 3
#define PKB 72                    // B smem pitch (halves)
#define B_BY (BKg * PKB * 2)      // 4608 bytes per array
#define STG_BY (2 * B_BY)         // 9216 (hi + lo)
#define SMEM_TOT (NST * STG_BY)   // 27648

template <int EPI>
__global__ __launch_bounds__(256, 2)
void gemm_split_kernel(const __half* __restrict__ Ahi,  // [M][K]
                       const __half* __restrict__ Alo,
                       const __half* __restrict__ Bhi,  // [batch][K][N]
                       const __half* __restrict__ Blo,
                       float* __restrict__ Cf,
                       __half* __restrict__ Chi,
                       __half* __restrict__ Clo,
                       int M, int Nfull,
                       const float* __restrict__ bias,
                       const float* __restrict__ gamma,
                       const float* __restrict__ beta,
                       const float* __restrict__ mean,
                       const float* __restrict__ var,
                       const float* __restrict__ prelu_a)
{
    extern __shared__ __align__(16) char smem[];
    const uint32_t sbase = smem_u32(smem);

    const int tid  = threadIdx.x;
    const int lane = tid & 31;
    const int wid  = tid >> 5;
    const int wm   = wid & 3;            // M warp 0..3 (32 rows each)
    const int wn   = wid >> 2;           // N warp 0..1 (32 cols each)
    const int lane15 = lane & 15;
    const int hi8    = (lane & 16) >> 1; // 0 or 8
    const int g    = lane >> 2;
    const int t2   = (lane & 3) * 2;

    const int rowBase = blockIdx.x * BMg;
    const int colBase = blockIdx.y * BNg;
    const int batch   = blockIdx.z;
    const __half* BhiP = Bhi + (size_t)batch * KDIM * Nfull;
    const __half* BloP = Blo + (size_t)batch * KDIM * Nfull;

    // A fragment row pointers (4 rows per thread: base + {0,8,16,24}), clamped
    const int rbase = rowBase + wm * 32 + g;
    const __half* pH[4];
    const __half* pL[4];
#pragma unroll
    for (int i = 0; i < 4; i++) {
        int rr = rbase + i * 8;
        int rc = (rr < M) ? rr : 0;
        pH[i] = Ahi + (size_t)rc * KDIM + t2;
        pL[i] = Alo + (size_t)rc * KDIM + t2;
    }

    // B cp.async indices: 32 k-rows x 128B (8 chunks of 16B) = 256; 1/thread
    const int b_kr = tid >> 3;           // 0..31
    const int b_nq = tid & 7;            // 16B chunk along n

    auto issue = [&](int ch, int s) {
        const int kc = ch * BKg;
        const uint32_t stg = sbase + s * STG_BY;
        const uint32_t bdst = stg + b_kr * (PKB * 2) + b_nq * 16;
        const size_t  bsrc = (size_t)(kc + b_kr) * Nfull + colBase + b_nq * 8;
        CP_ASYNC16(bdst,        BhiP + bsrc, 16u);
        CP_ASYNC16(bdst + B_BY, BloP + bsrc, 16u);
        CP_COMMIT();
    };

    float acc[2][4][4];
#pragma unroll
    for (int mt = 0; mt < 2; mt++)
#pragma unroll
        for (int nt = 0; nt < 4; nt++)
#pragma unroll
            for (int i = 0; i < 4; i++) acc[mt][nt][i] = 0.f;

    // prologue: NST-1 = 2 chunks in flight
    issue(0, 0); issue(1, 1);

    for (int c = 0; c < NCH; c++) {
        const int kc = c * BKg;

        // A fragments for this chunk: 32 independent LDG.32 (L2-resident),
        // all issued before any consumer -> deep MLP, latency hidden.
        uint32_t ah[2][2][4], al[2][2][4];   // [ks][mt][frag]
#pragma unroll
        for (int ks = 0; ks < 2; ks++) {
            const int ko = kc + ks * 16;
#pragma unroll
            for (int mt = 0; mt < 2; mt++) {
                ah[ks][mt][0] = *(const uint32_t*)(pH[mt * 2 + 0] + ko);
                ah[ks][mt][1] = *(const uint32_t*)(pH[mt * 2 + 1] + ko);
                ah[ks][mt][2] = *(const uint32_t*)(pH[mt * 2 + 0] + ko + 8);
                ah[ks][mt][3] = *(const uint32_t*)(pH[mt * 2 + 1] + ko + 8);
                al[ks][mt][0] = *(const uint32_t*)(pL[mt * 2 + 0] + ko);
                al[ks][mt][1] = *(const uint32_t*)(pL[mt * 2 + 1] + ko);
                al[ks][mt][2] = *(const uint32_t*)(pL[mt * 2 + 0] + ko + 8);
                al[ks][mt][3] = *(const uint32_t*)(pL[mt * 2 + 1] + ko + 8);
            }
        }

        if (c < NCH - 1) asm volatile("cp.async.wait_group 1;");
        else             asm volatile("cp.async.wait_group 0;");
        __syncthreads();                       // stage c ready; prev compute drained
        if (c + 2 < NCH) issue(c + 2, (c + 2) % NST);

        const int s = c % NST;
        const uint32_t bHiB = sbase + s * STG_BY;
        const uint32_t bLoB = bHiB + B_BY;

#pragma unroll
        for (int ks = 0; ks < 2; ks++) {
            const int k0 = ks * 16;
            uint32_t bh[2][4], bl[2][4];
#pragma unroll
            for (int nb = 0; nb < 2; nb++) {
                int nn   = wn * 32 + nb * 16 + hi8;
                int krow = k0 + lane15;
                uint32_t off = krow * (PKB * 2) + nn * 2;
                LDSM4T(bh[nb], bHiB + off);
                LDSM4T(bl[nb], bLoB + off);
            }
#pragma unroll
            for (int nb = 0; nb < 2; nb++)
#pragma unroll
                for (int ng = 0; ng < 2; ng++) {
                    uint32_t b0h = bh[nb][2 * ng], b1h = bh[nb][2 * ng + 1];
                    uint32_t b0l = bl[nb][2 * ng], b1l = bl[nb][2 * ng + 1];
#pragma unroll
                    for (int mt = 0; mt < 2; mt++) {
                        float* C = acc[mt][nb * 2 + ng];
                        MMA16816(C, ah[ks][mt], b0h, b1h);   // hi*hi
                        MMA16816(C, ah[ks][mt], b0l, b1l);   // hi*lo
                        MMA16816(C, al[ks][mt], b0h, b1h);   // lo*hi
                    }
                }
        }
    }

    // ---- epilogue (N always in-bounds: 3136 % 64 == 0) ----
#pragma unroll
    for (int mt = 0; mt < 2; mt++) {
        int r0 = rowBase + wm * 32 + mt * 16 + g;
#pragma unroll
        for (int half_ = 0; half_ < 2; half_++) {
            int rr = r0 + half_ * 8;
            if (rr >= M) continue;
            float bb = bias[rr];
            float sc = 0.f, mn = 0.f, bt = 0.f, aa = 0.f;
            if (EPI == 1) {
                sc = gamma[rr] * rsqrtf(var[rr] + EPSc);
                mn = mean[rr];
                bt = beta[rr];
                aa = prelu_a[0];
            }
#pragma unroll
            for (int nt = 0; nt < 4; nt++) {
                int col = colBase + wn * 32 + nt * 8 + t2;
                float v0 = acc[mt][nt][half_ * 2 + 0] + bb;
                float v1 = acc[mt][nt][half_ * 2 + 1] + bb;
                if (EPI == 1) {
                    v0 = (v0 - mn) * sc + bt;
                    v1 = (v1 - mn) * sc + bt;
                    v0 = v0 > 0.f ? v0 : aa * v0;
                    v1 = v1 > 0.f ? v1 : aa * v1;
                    uint32_t hw_, lw_;
                    split2(v0, v1, hw_, lw_);
                    size_t idx = ((size_t)batch * M + rr) * Nfull + col;
                    *(uint32_t*)(Chi + idx) = hw_;
                    *(uint32_t*)(Clo + idx) = lw_;
                } else {
                    size_t idx = ((size_t)batch * M + rr) * Nfull + col;
                    *(float2*)(Cf + idx) = make_float2(v0, v1);
                }
            }
        }
    }
}

// ---------------------------------------------------------------------------
// Involution aggregation — ONE barrier per block (R7 version, kept).
// ---------------------------------------------------------------------------
#define TH 4
#define HALO_R (TH + 6)           // 10
#define HALO_C 62
#define HALO_P 64                 // smem pitch

__global__ __launch_bounds__(256)
void involution_kernel(const float* __restrict__ x,
                       const float* __restrict__ ker,
                       float* __restrict__ out)
{
    __shared__ float xs[CG][HALO_R][HALO_P];   // 40 KB

    const int tileRow = blockIdx.x;
    const int g = blockIdx.y;
    const int b = blockIdx.z;
    const int tid = threadIdx.x;

    const int h0 = tileRow * TH;
    const bool active = tid < TH * Wc;          // 224
    const int r  = tid / Wc;
    const int cw = tid % Wc;
    const int h  = h0 + r;

    float kreg[KK];
    if (active) {
        const float* kp = ker + (((size_t)b * GK + g * KK) * HW) + h * Wc + cw;
#pragma unroll
        for (int idx = 0; idx < KK; idx++) kreg[idx] = kp[(size_t)idx * HW];
    }

    const float* xg = x + ((size_t)b * Cc + g * CG) * HW;
    for (int i = tid; i < CG * HALO_R * HALO_C; i += 256) {
        int ch  = i / (HALO_R * HALO_C);
        int rem = i - ch * (HALO_R * HALO_C);
        int rr  = rem / HALO_C;
        int cc  = rem - rr * HALO_C;
        int gh  = h0 - 3 + rr;
        int gw  = cc - 3;
        float v = 0.f;
        if (gh >= 0 && gh < Hc && gw >= 0 && gw < Wc)
            v = xg[(size_t)ch * HW + gh * Wc + gw];
        xs[ch][rr][cc] = v;
    }
    __syncthreads();

    if (active) {
        float* op = out + (((size_t)b * Cc + g * CG) * Hc + h) * Wc + cw;
#pragma unroll 4
        for (int ci = 0; ci < CG; ci++) {
            float a = 0.f;
#pragma unroll
            for (int i = 0; i < Kc; i++)
#pragma unroll
                for (int j = 0; j < Kc; j++)
                    a += xs[ci][r + i][cw + j] * kreg[i * Kc + j];
            op[(size_t)ci * HW] = a;
        }
    }
}

// ---------------------------------------------------------------------------
// Launch
// ---------------------------------------------------------------------------
extern "C" void kernel_launch(void* const* d_in, const int* in_sizes, int n_in,
                              void* d_out, int out_size)
{
    const float* x        = (const float*)d_in[0];
    const float* reduce_w = (const float*)d_in[1];
    const float* reduce_b = (const float*)d_in[2];
    const float* bn_gamma = (const float*)d_in[3];
    const float* bn_beta  = (const float*)d_in[4];
    const float* bn_mean  = (const float*)d_in[5];
    const float* bn_var   = (const float*)d_in[6];
    const float* prelu_a  = (const float*)d_in[7];
    const float* span_w   = (const float*)d_in[8];
    const float* span_b   = (const float*)d_in[9];
    float* out = (float*)d_out;

    __half *xh, *xl, *th, *tl, *w1h, *w1l, *w2h, *w2l;
    float* ker_buf;
    cudaGetSymbolAddress((void**)&xh, g_xh);
    cudaGetSymbolAddress((void**)&xl, g_xl);
    cudaGetSymbolAddress((void**)&th, g_th);
    cudaGetSymbolAddress((void**)&tl, g_tl);
    cudaGetSymbolAddress((void**)&w1h, g_w1h);
    cudaGetSymbolAddress((void**)&w1l, g_w1l);
    cudaGetSymbolAddress((void**)&w2h, g_w2h);
    cudaGetSymbolAddress((void**)&w2l, g_w2l);
    cudaGetSymbolAddress((void**)&ker_buf, g_ker);

    cudaFuncSetAttribute(gemm_split_kernel<1>,
                         cudaFuncAttributeMaxDynamicSharedMemorySize, SMEM_TOT);
    cudaFuncSetAttribute(gemm_split_kernel<2>,
                         cudaFuncAttributeMaxDynamicSharedMemorySize, SMEM_TOT);

    // 0) pre-split inputs
    {
        int n4 = Bc * Cc * HW / 4;
        split_kernel<<<(n4 + 255) / 256, 256>>>((const float4*)x,
                                                (uint2*)xh, (uint2*)xl, n4);
    }
    {
        int n4 = TNUM * Cc / 4;
        split_kernel<<<(n4 + 255) / 256, 256>>>((const float4*)reduce_w,
                                                (uint2*)w1h, (uint2*)w1l, n4);
    }
    {
        int n4 = GK * KDIM / 4;
        split_kernel<<<(n4 + 255) / 256, 256>>>((const float4*)span_w,
                                                (uint2*)w2h, (uint2*)w2l, n4);
    }

    // 1) GEMM1: T = BN_PReLU(reduce_w @ x), split output (feeds GEMM2)
    {
        dim3 grid(TNUM / BMg, HW / BNg, Bc);           // 2 x 49 x 4
        gemm_split_kernel<1><<<grid, 256, SMEM_TOT>>>(
            w1h, w1l, xh, xl,
            nullptr, th, tl,
            TNUM, HW,
            reduce_b, bn_gamma, bn_beta, bn_mean, bn_var, prelu_a);
    }
    // 2) GEMM2: KER = span_w @ T + span_b (fp32 out)
    {
        dim3 grid((GK + BMg - 1) / BMg, HW / BNg, Bc); // 7 x 49 x 4
        gemm_split_kernel<2><<<grid, 256, SMEM_TOT>>>(
            w2h, w2l, th, tl,
            ker_buf, nullptr, nullptr,
            GK, HW,
            span_b, nullptr, nullptr, nullptr, nullptr, nullptr);
    }
    // 3) involution aggregation
    {
        dim3 grid(Hc / TH, Gc, Bc);
        involution_kernel<<<grid, 256>>>(x, ker_buf, out);
    }
}

// round 9
// speedup vs baseline: 1.4054x; 1.4054x over previous
#include <cuda_runtime.h>
#include <cuda_fp16.h>
#include <cstdint>

// ---------------------------------------------------------------------------
// Problem constants
// ---------------------------------------------------------------------------
#define Bc    4
#define Cc    256
#define Hc    56
#define Wc    56
#define Gc    16
#define Kc    7
#define TNUM  256
#define HW    (Hc * Wc)          // 3136
#define CG    (Cc / Gc)          // 16
#define KK    (Kc * Kc)          // 49
#define GK    (Gc * KK)          // 784
#define EPSc  1e-5f
#define KDIM  256

// ---------------------------------------------------------------------------
// Scratch (no runtime allocation allowed)
// ---------------------------------------------------------------------------
__device__ __half g_xh[Bc * Cc * HW];
__device__ __half g_xl[Bc * Cc * HW];
__device__ __half g_th[Bc * TNUM * HW];
__device__ __half g_tl[Bc * TNUM * HW];
__device__ __half g_w1h[TNUM * Cc];
__device__ __half g_w1l[TNUM * Cc];
__device__ __half g_w2h[GK * KDIM];
__device__ __half g_w2l[GK * KDIM];
__device__ float  g_ker[Bc * GK * HW];

// ---------------------------------------------------------------------------
// helpers
// ---------------------------------------------------------------------------
__device__ __forceinline__ void split2(float x, float y,
                                       uint32_t& hi, uint32_t& lo) {
    __half hx = __float2half_rn(x);
    __half hy = __float2half_rn(y);
    __half lx = __float2half_rn(x - __half2float(hx));
    __half ly = __float2half_rn(y - __half2float(hy));
    hi = (uint32_t)__half_as_ushort(hx) | ((uint32_t)__half_as_ushort(hy) << 16);
    lo = (uint32_t)__half_as_ushort(lx) | ((uint32_t)__half_as_ushort(ly) << 16);
}

__device__ __forceinline__ uint32_t smem_u32(const void* p) {
    uint32_t a;
    asm("{ .reg .u64 t; cvta.to.shared.u64 t, %1; cvt.u32.u64 %0, t; }"
        : "=r"(a) : "l"(p));
    return a;
}

#define MMA16816(Cr, Ar, B0, B1)                                           \
    asm volatile(                                                          \
        "mma.sync.aligned.m16n8k16.row.col.f32.f16.f16.f32 "              \
        "{%0,%1,%2,%3}, {%4,%5,%6,%7}, {%8,%9}, {%0,%1,%2,%3};"           \
        : "+f"((Cr)[0]), "+f"((Cr)[1]), "+f"((Cr)[2]), "+f"((Cr)[3])       \
        : "r"((Ar)[0]), "r"((Ar)[1]), "r"((Ar)[2]), "r"((Ar)[3]),          \
          "r"(B0), "r"(B1))

#define LDSM4(R, addr)                                                     \
    asm volatile("ldmatrix.sync.aligned.m8n8.x4.shared.b16 "               \
        "{%0,%1,%2,%3}, [%4];"                                             \
        : "=r"((R)[0]), "=r"((R)[1]), "=r"((R)[2]), "=r"((R)[3])           \
        : "r"(addr))

#define LDSM4T(R, addr)                                                    \
    asm volatile("ldmatrix.sync.aligned.m8n8.x4.trans.shared.b16 "         \
        "{%0,%1,%2,%3}, [%4];"                                             \
        : "=r"((R)[0]), "=r"((R)[1]), "=r"((R)[2]), "=r"((R)[3])           \
        : "r"(addr))

#define CP_ASYNC16(dst, src, sz)                                           \
    asm volatile("cp.async.cg.shared.global [%0], [%1], 16, %2;"           \
        :: "r"(dst), "l"(src), "r"(sz))
#define CP_COMMIT() asm volatile("cp.async.commit_group;")

// ---------------------------------------------------------------------------
// fp32 -> fp16 hi/lo split (elementwise, float4-vectorized)
// ---------------------------------------------------------------------------
__global__ __launch_bounds__(256)
void split_kernel(const float4* __restrict__ src,
                  uint2* __restrict__ hi, uint2* __restrict__ lo, int n4)
{
    int i = blockIdx.x * blockDim.x + threadIdx.x;
    if (i >= n4) return;
    float4 v = src[i];
    uint32_t h0, l0, h1, l1;
    split2(v.x, v.y, h0, l0);
    split2(v.z, v.w, h1, l1);
    hi[i] = make_uint2(h0, h1);
    lo[i] = make_uint2(l0, l1);
}

// ---------------------------------------------------------------------------
// Split-fp16 HMMA GEMM, cp.async + ldmatrix, 2 CTAs/SM, ONE barrier/chunk.
// R7 structure; A-fragment LDSMs hoisted ahead of the ks loop so frag loads
// overlap MMAs (breaks the LDSM-burst / MMA-burst phase lock).
//   D[M,N] = A[M,K]*B[K,N], K=256.  3 MMAs per k-step (hh+hl+lh).
// Block: 256 thr (8 warps, 4Mx2N), tile 128x64, BK=32, 3-stage ring (89 KB).
// ---------------------------------------------------------------------------
#define BMg 128
#define BNg 64
#define BKg 32
#define NCH (KDIM / BKg)          // 8
#define NST 3
#define PKA 40                    // A smem pitch (halves)
#define PKB 72                    // B smem pitch (halves)
#define A_BY (BMg * PKA * 2)      // 10240
#define B_BY (BKg * PKB * 2)      // 4608
#define STG_BY (2 * A_BY + 2 * B_BY)   // 29696
#define SMEM_TOT (NST * STG_BY)        // 89088

template <int EPI>
__global__ __launch_bounds__(256, 2)
void gemm_split_kernel(const __half* __restrict__ Ahi,  // [M][K]
                       const __half* __restrict__ Alo,
                       const __half* __restrict__ Bhi,  // [batch][K][N]
                       const __half* __restrict__ Blo,
                       float* __restrict__ Cf,
                       __half* __restrict__ Chi,
                       __half* __restrict__ Clo,
                       int M, int Nfull,
                       const float* __restrict__ bias,
                       const float* __restrict__ gamma,
                       const float* __restrict__ beta,
                       const float* __restrict__ mean,
                       const float* __restrict__ var,
                       const float* __restrict__ prelu_a)
{
    extern __shared__ __align__(16) char smem[];
    const uint32_t sbase = smem_u32(smem);

    const int tid  = threadIdx.x;
    const int lane = tid & 31;
    const int wid  = tid >> 5;
    const int wm   = wid & 3;            // M warp 0..3 (32 rows each)
    const int wn   = wid >> 2;           // N warp 0..1 (32 cols each)
    const int lane15 = lane & 15;
    const int hi8    = (lane & 16) >> 1; // 0 or 8
    const int g    = lane >> 2;
    const int t2   = (lane & 3) * 2;

    const int rowBase = blockIdx.x * BMg;
    const int colBase = blockIdx.y * BNg;
    const int batch   = blockIdx.z;
    const __half* BhiP = Bhi + (size_t)batch * KDIM * Nfull;
    const __half* BloP = Blo + (size_t)batch * KDIM * Nfull;

    // cp.async indices
    const int a_idx0 = tid;              // A chunk 0 of 2
    const int a_idx1 = tid + 256;        // A chunk 1 of 2
    const int b_kr = tid >> 3;           // 0..31
    const int b_nq = tid & 7;            // 16B chunk along n

    auto issue = [&](int ch, int s) {
        const int kc = ch * BKg;
        const uint32_t stg = sbase + s * STG_BY;
#pragma unroll
        for (int i = 0; i < 2; i++) {
            const int idx = i ? a_idx1 : a_idx0;
            const int row = idx >> 2;
            const int kq  = idx & 3;
            const int gm  = rowBase + row;
            const uint32_t sz = (gm < M) ? 16u : 0u;
            const int gmc = (gm < M) ? gm : 0;
            const uint32_t adst = stg + row * (PKA * 2) + kq * 16;
            const size_t  asrc = (size_t)gmc * KDIM + kc + kq * 8;
            CP_ASYNC16(adst,        Ahi + asrc, sz);
            CP_ASYNC16(adst + A_BY, Alo + asrc, sz);
        }
        const uint32_t bdst = stg + 2 * A_BY + b_kr * (PKB * 2) + b_nq * 16;
        const size_t  bsrc = (size_t)(kc + b_kr) * Nfull + colBase + b_nq * 8;
        CP_ASYNC16(bdst,        BhiP + bsrc, 16u);
        CP_ASYNC16(bdst + B_BY, BloP + bsrc, 16u);
        CP_COMMIT();
    };

    float acc[2][4][4];
#pragma unroll
    for (int mt = 0; mt < 2; mt++)
#pragma unroll
        for (int nt = 0; nt < 4; nt++)
#pragma unroll
            for (int i = 0; i < 4; i++) acc[mt][nt][i] = 0.f;

    // prologue: NST-1 = 2 chunks in flight
    issue(0, 0); issue(1, 1);

    for (int c = 0; c < NCH; c++) {
        if (c < NCH - 1) asm volatile("cp.async.wait_group 1;");
        else             asm volatile("cp.async.wait_group 0;");
        __syncthreads();                       // stage c ready; prev compute drained
        if (c + 2 < NCH) issue(c + 2, (c + 2) % NST);

        const int s = c % NST;
        const uint32_t aHiB = sbase + s * STG_BY;
        const uint32_t aLoB = aHiB + A_BY;
        const uint32_t bHiB = aHiB + 2 * A_BY;
        const uint32_t bLoB = bHiB + B_BY;

        // ---- hoist: ALL A fragments for both k-steps before any MMA ----
        uint32_t ah[2][2][4], al[2][2][4];     // [ks][mt][frag]
#pragma unroll
        for (int ks = 0; ks < 2; ks++) {
            const int k0 = ks * 16;
#pragma unroll
            for (int mt = 0; mt < 2; mt++) {
                int row = wm * 32 + mt * 16 + lane15;
                uint32_t off = row * (PKA * 2) + (k0 + hi8) * 2;
                LDSM4(ah[ks][mt], aHiB + off);
                LDSM4(al[ks][mt], aLoB + off);
            }
        }

#pragma unroll
        for (int ks = 0; ks < 2; ks++) {
            const int k0 = ks * 16;
            uint32_t bh[2][4], bl[2][4];
#pragma unroll
            for (int nb = 0; nb < 2; nb++) {
                int nn   = wn * 32 + nb * 16 + hi8;
                int krow = k0 + lane15;
                uint32_t off = krow * (PKB * 2) + nn * 2;
                LDSM4T(bh[nb], bHiB + off);
                LDSM4T(bl[nb], bLoB + off);
            }
#pragma unroll
            for (int nb = 0; nb < 2; nb++)
#pragma unroll
                for (int ng = 0; ng < 2; ng++) {
                    uint32_t b0h = bh[nb][2 * ng], b1h = bh[nb][2 * ng + 1];
                    uint32_t b0l = bl[nb][2 * ng], b1l = bl[nb][2 * ng + 1];
#pragma unroll
                    for (int mt = 0; mt < 2; mt++) {
                        float* C = acc[mt][nb * 2 + ng];
                        MMA16816(C, ah[ks][mt], b0h, b1h);   // hi*hi
                        MMA16816(C, ah[ks][mt], b0l, b1l);   // hi*lo
                        MMA16816(C, al[ks][mt], b0h, b1h);   // lo*hi
                    }
                }
        }
    }

    // ---- epilogue (N always in-bounds: 3136 % 64 == 0) ----
#pragma unroll
    for (int mt = 0; mt < 2; mt++) {
        int r0 = rowBase + wm * 32 + mt * 16 + g;
#pragma unroll
        for (int half_ = 0; half_ < 2; half_++) {
            int rr = r0 + half_ * 8;
            if (rr >= M) continue;
            float bb = bias[rr];
            float sc = 0.f, mn = 0.f, bt = 0.f, aa = 0.f;
            if (EPI == 1) {
                sc = gamma[rr] * rsqrtf(var[rr] + EPSc);
                mn = mean[rr];
                bt = beta[rr];
                aa = prelu_a[0];
            }
#pragma unroll
            for (int nt = 0; nt < 4; nt++) {
                int col = colBase + wn * 32 + nt * 8 + t2;
                float v0 = acc[mt][nt][half_ * 2 + 0] + bb;
                float v1 = acc[mt][nt][half_ * 2 + 1] + bb;
                if (EPI == 1) {
                    v0 = (v0 - mn) * sc + bt;
                    v1 = (v1 - mn) * sc + bt;
                    v0 = v0 > 0.f ? v0 : aa * v0;
                    v1 = v1 > 0.f ? v1 : aa * v1;
                    uint32_t hw_, lw_;
                    split2(v0, v1, hw_, lw_);
                    size_t idx = ((size_t)batch * M + rr) * Nfull + col;
                    *(uint32_t*)(Chi + idx) = hw_;
                    *(uint32_t*)(Clo + idx) = lw_;
                } else {
                    size_t idx = ((size_t)batch * M + rr) * Nfull + col;
                    *(float2*)(Cf + idx) = make_float2(v0, v1);
                }
            }
        }
    }
}

// ---------------------------------------------------------------------------
// Involution aggregation — ONE barrier per block (R7 version, kept).
// ---------------------------------------------------------------------------
#define TH 4
#define HALO_R (TH + 6)           // 10
#define HALO_C 62
#define HALO_P 64                 // smem pitch

__global__ __launch_bounds__(256)
void involution_kernel(const float* __restrict__ x,
                       const float* __restrict__ ker,
                       float* __restrict__ out)
{
    __shared__ float xs[CG][HALO_R][HALO_P];   // 40 KB

    const int tileRow = blockIdx.x;
    const int g = blockIdx.y;
    const int b = blockIdx.z;
    const int tid = threadIdx.x;

    const int h0 = tileRow * TH;
    const bool active = tid < TH * Wc;          // 224
    const int r  = tid / Wc;
    const int cw = tid % Wc;
    const int h  = h0 + r;

    float kreg[KK];
    if (active) {
        const float* kp = ker + (((size_t)b * GK + g * KK) * HW) + h * Wc + cw;
#pragma unroll
        for (int idx = 0; idx < KK; idx++) kreg[idx] = kp[(size_t)idx * HW];
    }

    const float* xg = x + ((size_t)b * Cc + g * CG) * HW;
    for (int i = tid; i < CG * HALO_R * HALO_C; i += 256) {
        int ch  = i / (HALO_R * HALO_C);
        int rem = i - ch * (HALO_R * HALO_C);
        int rr  = rem / HALO_C;
        int cc  = rem - rr * HALO_C;
        int gh  = h0 - 3 + rr;
        int gw  = cc - 3;
        float v = 0.f;
        if (gh >= 0 && gh < Hc && gw >= 0 && gw < Wc)
            v = xg[(size_t)ch * HW + gh * Wc + gw];
        xs[ch][rr][cc] = v;
    }
    __syncthreads();

    if (active) {
        float* op = out + (((size_t)b * Cc + g * CG) * Hc + h) * Wc + cw;
#pragma unroll 4
        for (int ci = 0; ci < CG; ci++) {
            float a = 0.f;
#pragma unroll
            for (int i = 0; i < Kc; i++)
#pragma unroll
                for (int j = 0; j < Kc; j++)
                    a += xs[ci][r + i][cw + j] * kreg[i * Kc + j];
            op[(size_t)ci * HW] = a;
        }
    }
}

// ---------------------------------------------------------------------------
// Launch
// ---------------------------------------------------------------------------
extern "C" void kernel_launch(void* const* d_in, const int* in_sizes, int n_in,
                              void* d_out, int out_size)
{
    const float* x        = (const float*)d_in[0];
    const float* reduce_w = (const float*)d_in[1];
    const float* reduce_b = (const float*)d_in[2];
    const float* bn_gamma = (const float*)d_in[3];
    const float* bn_beta  = (const float*)d_in[4];
    const float* bn_mean  = (const float*)d_in[5];
    const float* bn_var   = (const float*)d_in[6];
    const float* prelu_a  = (const float*)d_in[7];
    const float* span_w   = (const float*)d_in[8];
    const float* span_b   = (const float*)d_in[9];
    float* out = (float*)d_out;

    __half *xh, *xl, *th, *tl, *w1h, *w1l, *w2h, *w2l;
    float* ker_buf;
    cudaGetSymbolAddress((void**)&xh, g_xh);
    cudaGetSymbolAddress((void**)&xl, g_xl);
    cudaGetSymbolAddress((void**)&th, g_th);
    cudaGetSymbolAddress((void**)&tl, g_tl);
    cudaGetSymbolAddress((void**)&w1h, g_w1h);
    cudaGetSymbolAddress((void**)&w1l, g_w1l);
    cudaGetSymbolAddress((void**)&w2h, g_w2h);
    cudaGetSymbolAddress((void**)&w2l, g_w2l);
    cudaGetSymbolAddress((void**)&ker_buf, g_ker);

    cudaFuncSetAttribute(gemm_split_kernel<1>,
                         cudaFuncAttributeMaxDynamicSharedMemorySize, SMEM_TOT);
    cudaFuncSetAttribute(gemm_split_kernel<2>,
                         cudaFuncAttributeMaxDynamicSharedMemorySize, SMEM_TOT);

    // 0) pre-split inputs
    {
        int n4 = Bc * Cc * HW / 4;
        split_kernel<<<(n4 + 255) / 256, 256>>>((const float4*)x,
                                                (uint2*)xh, (uint2*)xl, n4);
    }
    {
        int n4 = TNUM * Cc / 4;
        split_kernel<<<(n4 + 255) / 256, 256>>>((const float4*)reduce_w,
                                                (uint2*)w1h, (uint2*)w1l, n4);
    }
    {
        int n4 = GK * KDIM / 4;
        split_kernel<<<(n4 + 255) / 256, 256>>>((const float4*)span_w,
                                                (uint2*)w2h, (uint2*)w2l, n4);
    }

    // 1) GEMM1: T = BN_PReLU(reduce_w @ x), split output (feeds GEMM2)
    {
        dim3 grid(TNUM / BMg, HW / BNg, Bc);           // 2 x 49 x 4
        gemm_split_kernel<1><<<grid, 256, SMEM_TOT>>>(
            w1h, w1l, xh, xl,
            nullptr, th, tl,
            TNUM, HW,
            reduce_b, bn_gamma, bn_beta, bn_mean, bn_var, prelu_a);
    }
    // 2) GEMM2: KER = span_w @ T + span_b (fp32 out)
    {
        dim3 grid((GK + BMg - 1) / BMg, HW / BNg, Bc); // 7 x 49 x 4
        gemm_split_kernel<2><<<grid, 256, SMEM_TOT>>>(
            w2h, w2l, th, tl,
            ker_buf, nullptr, nullptr,
            GK, HW,
            span_b, nullptr, nullptr, nullptr, nullptr, nullptr);
    }
    // 3) involution aggregation
    {
        dim3 grid(Hc / TH, Gc, Bc);
        involution_kernel<<<grid, 256>>>(x, ker_buf, out);
    }
}

// round 11
// speedup vs baseline: 1.4635x; 1.0413x over previous
#include <cuda_runtime.h>
#include <cuda_fp16.h>
#include <cstdint>

// ---------------------------------------------------------------------------
// Problem constants
// ---------------------------------------------------------------------------
#define Bc    4
#define Cc    256
#define Hc    56
#define Wc    56
#define Gc    16
#define Kc    7
#define TNUM  256
#define HW    (Hc * Wc)          // 3136
#define CG    (Cc / Gc)          // 16
#define KK    (Kc * Kc)          // 49
#define GK    (Gc * KK)          // 784
#define EPSc  1e-5f
#define KDIM  256

// ---------------------------------------------------------------------------
// Scratch (no runtime allocation allowed)
// ---------------------------------------------------------------------------
__device__ __half g_xh[Bc * Cc * HW];
__device__ __half g_xl[Bc * Cc * HW];
__device__ __half g_th[Bc * TNUM * HW];
__device__ __half g_tl[Bc * TNUM * HW];
__device__ __half g_w1h[TNUM * Cc];
__device__ __half g_w1l[TNUM * Cc];
__device__ __half g_w2h[GK * KDIM];
__device__ __half g_w2l[GK * KDIM];
__device__ float  g_ker[Bc * GK * HW];

// ---------------------------------------------------------------------------
// helpers
// ---------------------------------------------------------------------------
__device__ __forceinline__ void split2(float x, float y,
                                       uint32_t& hi, uint32_t& lo) {
    __half hx = __float2half_rn(x);
    __half hy = __float2half_rn(y);
    __half lx = __float2half_rn(x - __half2float(hx));
    __half ly = __float2half_rn(y - __half2float(hy));
    hi = (uint32_t)__half_as_ushort(hx) | ((uint32_t)__half_as_ushort(hy) << 16);
    lo = (uint32_t)__half_as_ushort(lx) | ((uint32_t)__half_as_ushort(ly) << 16);
}

__device__ __forceinline__ uint32_t smem_u32(const void* p) {
    uint32_t a;
    asm("{ .reg .u64 t; cvta.to.shared.u64 t, %1; cvt.u32.u64 %0, t; }"
        : "=r"(a) : "l"(p));
    return a;
}

#define MMA16816(Cr, Ar, B0, B1)                                           \
    asm volatile(                                                          \
        "mma.sync.aligned.m16n8k16.row.col.f32.f16.f16.f32 "              \
        "{%0,%1,%2,%3}, {%4,%5,%6,%7}, {%8,%9}, {%0,%1,%2,%3};"           \
        : "+f"((Cr)[0]), "+f"((Cr)[1]), "+f"((Cr)[2]), "+f"((Cr)[3])       \
        : "r"((Ar)[0]), "r"((Ar)[1]), "r"((Ar)[2]), "r"((Ar)[3]),          \
          "r"(B0), "r"(B1))

#define LDSM4(R, addr)                                                     \
    asm volatile("ldmatrix.sync.aligned.m8n8.x4.shared.b16 "               \
        "{%0,%1,%2,%3}, [%4];"                                             \
        : "=r"((R)[0]), "=r"((R)[1]), "=r"((R)[2]), "=r"((R)[3])           \
        : "r"(addr))

#define LDSM4T(R, addr)                                                    \
    asm volatile("ldmatrix.sync.aligned.m8n8.x4.trans.shared.b16 "         \
        "{%0,%1,%2,%3}, [%4];"                                             \
        : "=r"((R)[0]), "=r"((R)[1]), "=r"((R)[2]), "=r"((R)[3])           \
        : "r"(addr))

#define CP_ASYNC16(dst, src, sz)                                           \
    asm volatile("cp.async.cg.shared.global [%0], [%1], 16, %2;"           \
        :: "r"(dst), "l"(src), "r"(sz))
#define CP_COMMIT() asm volatile("cp.async.commit_group;")

// ---------------------------------------------------------------------------
// fp32 -> fp16 hi/lo split (elementwise, float4-vectorized)
// ---------------------------------------------------------------------------
__global__ __launch_bounds__(256)
void split_kernel(const float4* __restrict__ src,
                  uint2* __restrict__ hi, uint2* __restrict__ lo, int n4)
{
    int i = blockIdx.x * blockDim.x + threadIdx.x;
    if (i >= n4) return;
    float4 v = src[i];
    uint32_t h0, l0, h1, l1;
    split2(v.x, v.y, h0, l0);
    split2(v.z, v.w, h1, l1);
    hi[i] = make_uint2(h0, h1);
    lo[i] = make_uint2(l0, l1);
}

// ---------------------------------------------------------------------------
// Split-fp16 HMMA GEMM, cp.async + ldmatrix, 3 CTAs/SM, ONE barrier/chunk.
// R7 inner loop; 2-stage ring (59.4 KB) so three CTAs co-reside per SM —
// warp supply covers barrier/wait gaps that capped tensor pipe at ~30%.
//   D[M,N] = A[M,K]*B[K,N], K=256.  3 MMAs per k-step (hh+hl+lh).
// Block: 256 thr (8 warps, 4Mx2N), tile 128x64, BK=32.
// ---------------------------------------------------------------------------
#define BMg 128
#define BNg 64
#define BKg 32
#define NCH (KDIM / BKg)          // 8
#define NST 2
#define PKA 40                    // A smem pitch (halves)
#define PKB 72                    // B smem pitch (halves)
#define A_BY (BMg * PKA * 2)      // 10240
#define B_BY (BKg * PKB * 2)      // 4608
#define STG_BY (2 * A_BY + 2 * B_BY)   // 29696
#define SMEM_TOT (NST * STG_BY)        // 59392

template <int EPI>
__global__ __launch_bounds__(256, 3)
void gemm_split_kernel(const __half* __restrict__ Ahi,  // [M][K]
                       const __half* __restrict__ Alo,
                       const __half* __restrict__ Bhi,  // [batch][K][N]
                       const __half* __restrict__ Blo,
                       float* __restrict__ Cf,
                       __half* __restrict__ Chi,
                       __half* __restrict__ Clo,
                       int M, int Nfull,
                       const float* __restrict__ bias,
                       const float* __restrict__ gamma,
                       const float* __restrict__ beta,
                       const float* __restrict__ mean,
                       const float* __restrict__ var,
                       const float* __restrict__ prelu_a)
{
    extern __shared__ __align__(16) char smem[];
    const uint32_t sbase = smem_u32(smem);

    const int tid  = threadIdx.x;
    const int lane = tid & 31;
    const int wid  = tid >> 5;
    const int wm   = wid & 3;            // M warp 0..3 (32 rows each)
    const int wn   = wid >> 2;           // N warp 0..1 (32 cols each)
    const int lane15 = lane & 15;
    const int hi8    = (lane & 16) >> 1; // 0 or 8
    const int g    = lane >> 2;
    const int t2   = (lane & 3) * 2;

    const int rowBase = blockIdx.x * BMg;
    const int colBase = blockIdx.y * BNg;
    const int batch   = blockIdx.z;
    const __half* BhiP = Bhi + (size_t)batch * KDIM * Nfull;
    const __half* BloP = Blo + (size_t)batch * KDIM * Nfull;

    // cp.async indices
    const int a_idx0 = tid;              // A chunk 0 of 2
    const int a_idx1 = tid + 256;        // A chunk 1 of 2
    const int b_kr = tid >> 3;           // 0..31
    const int b_nq = tid & 7;            // 16B chunk along n

    auto issue = [&](int ch, int s) {
        const int kc = ch * BKg;
        const uint32_t stg = sbase + s * STG_BY;
#pragma unroll
        for (int i = 0; i < 2; i++) {
            const int idx = i ? a_idx1 : a_idx0;
            const int row = idx >> 2;
            const int kq  = idx & 3;
            const int gm  = rowBase + row;
            const uint32_t sz = (gm < M) ? 16u : 0u;
            const int gmc = (gm < M) ? gm : 0;
            const uint32_t adst = stg + row * (PKA * 2) + kq * 16;
            const size_t  asrc = (size_t)gmc * KDIM + kc + kq * 8;
            CP_ASYNC16(adst,        Ahi + asrc, sz);
            CP_ASYNC16(adst + A_BY, Alo + asrc, sz);
        }
        const uint32_t bdst = stg + 2 * A_BY + b_kr * (PKB * 2) + b_nq * 16;
        const size_t  bsrc = (size_t)(kc + b_kr) * Nfull + colBase + b_nq * 8;
        CP_ASYNC16(bdst,        BhiP + bsrc, 16u);
        CP_ASYNC16(bdst + B_BY, BloP + bsrc, 16u);
        CP_COMMIT();
    };

    float acc[2][4][4];
#pragma unroll
    for (int mt = 0; mt < 2; mt++)
#pragma unroll
        for (int nt = 0; nt < 4; nt++)
#pragma unroll
            for (int i = 0; i < 4; i++) acc[mt][nt][i] = 0.f;

    // prologue: 1 chunk in flight
    issue(0, 0);

    for (int c = 0; c < NCH; c++) {
        asm volatile("cp.async.wait_group 0;");
        __syncthreads();                       // stage c ready; prev compute drained
        if (c + 1 < NCH) issue(c + 1, (c + 1) % NST);  // other stage (freed last iter)

        const int s = c % NST;
        const uint32_t aHiB = sbase + s * STG_BY;
        const uint32_t aLoB = aHiB + A_BY;
        const uint32_t bHiB = aHiB + 2 * A_BY;
        const uint32_t bLoB = bHiB + B_BY;

#pragma unroll
        for (int ks = 0; ks < 2; ks++) {
            const int k0 = ks * 16;
            uint32_t ah[2][4], al[2][4], bh[2][4], bl[2][4];
#pragma unroll
            for (int mt = 0; mt < 2; mt++) {
                int row = wm * 32 + mt * 16 + lane15;
                uint32_t off = row * (PKA * 2) + (k0 + hi8) * 2;
                LDSM4(ah[mt], aHiB + off);
                LDSM4(al[mt], aLoB + off);
            }
#pragma unroll
            for (int nb = 0; nb < 2; nb++) {
                int nn   = wn * 32 + nb * 16 + hi8;
                int krow = k0 + lane15;
                uint32_t off = krow * (PKB * 2) + nn * 2;
                LDSM4T(bh[nb], bHiB + off);
                LDSM4T(bl[nb], bLoB + off);
            }
#pragma unroll
            for (int nb = 0; nb < 2; nb++)
#pragma unroll
                for (int ng = 0; ng < 2; ng++) {
                    uint32_t b0h = bh[nb][2 * ng], b1h = bh[nb][2 * ng + 1];
                    uint32_t b0l = bl[nb][2 * ng], b1l = bl[nb][2 * ng + 1];
#pragma unroll
                    for (int mt = 0; mt < 2; mt++) {
                        float* C = acc[mt][nb * 2 + ng];
                        MMA16816(C, ah[mt], b0h, b1h);   // hi*hi
                        MMA16816(C, ah[mt], b0l, b1l);   // hi*lo
                        MMA16816(C, al[mt], b0h, b1h);   // lo*hi
                    }
                }
        }
    }

    // ---- epilogue (N always in-bounds: 3136 % 64 == 0) ----
#pragma unroll
    for (int mt = 0; mt < 2; mt++) {
        int r0 = rowBase + wm * 32 + mt * 16 + g;
#pragma unroll
        for (int half_ = 0; half_ < 2; half_++) {
            int rr = r0 + half_ * 8;
            if (rr >= M) continue;
            float bb = bias[rr];
            float sc = 0.f, mn = 0.f, bt = 0.f, aa = 0.f;
            if (EPI == 1) {
                sc = gamma[rr] * rsqrtf(var[rr] + EPSc);
                mn = mean[rr];
                bt = beta[rr];
                aa = prelu_a[0];
            }
#pragma unroll
            for (int nt = 0; nt < 4; nt++) {
                int col = colBase + wn * 32 + nt * 8 + t2;
                float v0 = acc[mt][nt][half_ * 2 + 0] + bb;
                float v1 = acc[mt][nt][half_ * 2 + 1] + bb;
                if (EPI == 1) {
                    v0 = (v0 - mn) * sc + bt;
                    v1 = (v1 - mn) * sc + bt;
                    v0 = v0 > 0.f ? v0 : aa * v0;
                    v1 = v1 > 0.f ? v1 : aa * v1;
                    uint32_t hw_, lw_;
                    split2(v0, v1, hw_, lw_);
                    size_t idx = ((size_t)batch * M + rr) * Nfull + col;
                    *(uint32_t*)(Chi + idx) = hw_;
                    *(uint32_t*)(Clo + idx) = lw_;
                } else {
                    size_t idx = ((size_t)batch * M + rr) * Nfull + col;
                    *(float2*)(Cf + idx) = make_float2(v0, v1);
                }
            }
        }
    }
}

// ---------------------------------------------------------------------------
// Involution aggregation — ONE barrier per block (R7 version, kept).
// ---------------------------------------------------------------------------
#define TH 4
#define HALO_R (TH + 6)           // 10
#define HALO_C 62
#define HALO_P 64                 // smem pitch

__global__ __launch_bounds__(256)
void involution_kernel(const float* __restrict__ x,
                       const float* __restrict__ ker,
                       float* __restrict__ out)
{
    __shared__ float xs[CG][HALO_R][HALO_P];   // 40 KB

    const int tileRow = blockIdx.x;
    const int g = blockIdx.y;
    const int b = blockIdx.z;
    const int tid = threadIdx.x;

    const int h0 = tileRow * TH;
    const bool active = tid < TH * Wc;          // 224
    const int r  = tid / Wc;
    const int cw = tid % Wc;
    const int h  = h0 + r;

    float kreg[KK];
    if (active) {
        const float* kp = ker + (((size_t)b * GK + g * KK) * HW) + h * Wc + cw;
#pragma unroll
        for (int idx = 0; idx < KK; idx++) kreg[idx] = kp[(size_t)idx * HW];
    }

    const float* xg = x + ((size_t)b * Cc + g * CG) * HW;
    for (int i = tid; i < CG * HALO_R * HALO_C; i += 256) {
        int ch  = i / (HALO_R * HALO_C);
        int rem = i - ch * (HALO_R * HALO_C);
        int rr  = rem / HALO_C;
        int cc  = rem - rr * HALO_C;
        int gh  = h0 - 3 + rr;
        int gw  = cc - 3;
        float v = 0.f;
        if (gh >= 0 && gh < Hc && gw >= 0 && gw < Wc)
            v = xg[(size_t)ch * HW + gh * Wc + gw];
        xs[ch][rr][cc] = v;
    }
    __syncthreads();

    if (active) {
        float* op = out + (((size_t)b * Cc + g * CG) * Hc + h) * Wc + cw;
#pragma unroll 4
        for (int ci = 0; ci < CG; ci++) {
            float a = 0.f;
#pragma unroll
            for (int i = 0; i < Kc; i++)
#pragma unroll
                for (int j = 0; j < Kc; j++)
                    a += xs[ci][r + i][cw + j] * kreg[i * Kc + j];
            op[(size_t)ci * HW] = a;
        }
    }
}

// ---------------------------------------------------------------------------
// Launch
// ---------------------------------------------------------------------------
extern "C" void kernel_launch(void* const* d_in, const int* in_sizes, int n_in,
                              void* d_out, int out_size)
{
    const float* x        = (const float*)d_in[0];
    const float* reduce_w = (const float*)d_in[1];
    const float* reduce_b = (const float*)d_in[2];
    const float* bn_gamma = (const float*)d_in[3];
    const float* bn_beta  = (const float*)d_in[4];
    const float* bn_mean  = (const float*)d_in[5];
    const float* bn_var   = (const float*)d_in[6];
    const float* prelu_a  = (const float*)d_in[7];
    const float* span_w   = (const float*)d_in[8];
    const float* span_b   = (const float*)d_in[9];
    float* out = (float*)d_out;

    __half *xh, *xl, *th, *tl, *w1h, *w1l, *w2h, *w2l;
    float* ker_buf;
    cudaGetSymbolAddress((void**)&xh, g_xh);
    cudaGetSymbolAddress((void**)&xl, g_xl);
    cudaGetSymbolAddress((void**)&th, g_th);
    cudaGetSymbolAddress((void**)&tl, g_tl);
    cudaGetSymbolAddress((void**)&w1h, g_w1h);
    cudaGetSymbolAddress((void**)&w1l, g_w1l);
    cudaGetSymbolAddress((void**)&w2h, g_w2h);
    cudaGetSymbolAddress((void**)&w2l, g_w2l);
    cudaGetSymbolAddress((void**)&ker_buf, g_ker);

    cudaFuncSetAttribute(gemm_split_kernel<1>,
                         cudaFuncAttributeMaxDynamicSharedMemorySize, SMEM_TOT);
    cudaFuncSetAttribute(gemm_split_kernel<2>,
                         cudaFuncAttributeMaxDynamicSharedMemorySize, SMEM_TOT);

    // 0) pre-split inputs
    {
        int n4 = Bc * Cc * HW / 4;
        split_kernel<<<(n4 + 255) / 256, 256>>>((const float4*)x,
                                                (uint2*)xh, (uint2*)xl, n4);
    }
    {
        int n4 = TNUM * Cc / 4;
        split_kernel<<<(n4 + 255) / 256, 256>>>((const float4*)reduce_w,
                                                (uint2*)w1h, (uint2*)w1l, n4);
    }
    {
        int n4 = GK * KDIM / 4;
        split_kernel<<<(n4 + 255) / 256, 256>>>((const float4*)span_w,
                                                (uint2*)w2h, (uint2*)w2l, n4);
    }

    // 1) GEMM1: T = BN_PReLU(reduce_w @ x), split output (feeds GEMM2)
    {
        dim3 grid(TNUM / BMg, HW / BNg, Bc);           // 2 x 49 x 4
        gemm_split_kernel<1><<<grid, 256, SMEM_TOT>>>(
            w1h, w1l, xh, xl,
            nullptr, th, tl,
            TNUM, HW,
            reduce_b, bn_gamma, bn_beta, bn_mean, bn_var, prelu_a);
    }
    // 2) GEMM2: KER = span_w @ T + span_b (fp32 out)
    {
        dim3 grid((GK + BMg - 1) / BMg, HW / BNg, Bc); // 7 x 49 x 4
        gemm_split_kernel<2><<<grid, 256, SMEM_TOT>>>(
            w2h, w2l, th, tl,
            ker_buf, nullptr, nullptr,
            GK, HW,
            span_b, nullptr, nullptr, nullptr, nullptr, nullptr);
    }
    // 3) involution aggregation
    {
        dim3 grid(Hc / TH, Gc, Bc);
        involution_kernel<<<grid, 256>>>(x, ker_buf, out);
    }
}

// round 13
// speedup vs baseline: 1.4651x; 1.0011x over previous
#include <cuda_runtime.h>
#include <cuda_fp16.h>
#include <cstdint>

// ---------------------------------------------------------------------------
// Problem constants
// ---------------------------------------------------------------------------
#define Bc    4
#define Cc    256
#define Hc    56
#define Wc    56
#define Gc    16
#define Kc    7
#define TNUM  256
#define HW    (Hc * Wc)          // 3136
#define CG    (Cc / Gc)          // 16
#define KK    (Kc * Kc)          // 49
#define GK    (Gc * KK)          // 784
#define EPSc  1e-5f
#define KDIM  256

// ---------------------------------------------------------------------------
// Scratch (no runtime allocation allowed)
// ---------------------------------------------------------------------------
__device__ __half g_xh[Bc * Cc * HW];
__device__ __half g_xl[Bc * Cc * HW];
__device__ __half g_th[Bc * TNUM * HW];
__device__ __half g_tl[Bc * TNUM * HW];
__device__ __half g_w1h[TNUM * Cc];
__device__ __half g_w1l[TNUM * Cc];
__device__ __half g_w2h[GK * KDIM];
__device__ __half g_w2l[GK * KDIM];
__device__ float  g_ker[Bc * GK * HW];

// ---------------------------------------------------------------------------
// helpers
// ---------------------------------------------------------------------------
__device__ __forceinline__ void split2(float x, float y,
                                       uint32_t& hi, uint32_t& lo) {
    __half hx = __float2half_rn(x);
    __half hy = __float2half_rn(y);
    __half lx = __float2half_rn(x - __half2float(hx));
    __half ly = __float2half_rn(y - __half2float(hy));
    hi = (uint32_t)__half_as_ushort(hx) | ((uint32_t)__half_as_ushort(hy) << 16);
    lo = (uint32_t)__half_as_ushort(lx) | ((uint32_t)__half_as_ushort(ly) << 16);
}

__device__ __forceinline__ uint32_t smem_u32(const void* p) {
    uint32_t a;
    asm("{ .reg .u64 t; cvta.to.shared.u64 t, %1; cvt.u32.u64 %0, t; }"
        : "=r"(a) : "l"(p));
    return a;
}

// NOTE: non-volatile — register-only, no side effects; lets ptxas schedule
// around accumulator RAW chains.
#define MMA16816(Cr, Ar, B0, B1)                                           \
    asm("mma.sync.aligned.m16n8k16.row.col.f32.f16.f16.f32 "              \
        "{%0,%1,%2,%3}, {%4,%5,%6,%7}, {%8,%9}, {%0,%1,%2,%3};"           \
        : "+f"((Cr)[0]), "+f"((Cr)[1]), "+f"((Cr)[2]), "+f"((Cr)[3])       \
        : "r"((Ar)[0]), "r"((Ar)[1]), "r"((Ar)[2]), "r"((Ar)[3]),          \
          "r"(B0), "r"(B1))

#define LDSM4(R, addr)                                                     \
    asm volatile("ldmatrix.sync.aligned.m8n8.x4.shared.b16 "               \
        "{%0,%1,%2,%3}, [%4];"                                             \
        : "=r"((R)[0]), "=r"((R)[1]), "=r"((R)[2]), "=r"((R)[3])           \
        : "r"(addr))

#define LDSM4T(R, addr)                                                    \
    asm volatile("ldmatrix.sync.aligned.m8n8.x4.trans.shared.b16 "         \
        "{%0,%1,%2,%3}, [%4];"                                             \
        : "=r"((R)[0]), "=r"((R)[1]), "=r"((R)[2]), "=r"((R)[3])           \
        : "r"(addr))

#define CP_ASYNC16(dst, src, sz)                                           \
    asm volatile("cp.async.cg.shared.global [%0], [%1], 16, %2;"           \
        :: "r"(dst), "l"(src), "r"(sz))
#define CP_COMMIT() asm volatile("cp.async.commit_group;")

// ---------------------------------------------------------------------------
// fp32 -> fp16 hi/lo split (elementwise, float4-vectorized)
// ---------------------------------------------------------------------------
__global__ __launch_bounds__(256)
void split_kernel(const float4* __restrict__ src,
                  uint2* __restrict__ hi, uint2* __restrict__ lo, int n4)
{
    int i = blockIdx.x * blockDim.x + threadIdx.x;
    if (i >= n4) return;
    float4 v = src[i];
    uint32_t h0, l0, h1, l1;
    split2(v.x, v.y, h0, l0);
    split2(v.z, v.w, h1, l1);
    hi[i] = make_uint2(h0, h1);
    lo[i] = make_uint2(l0, l1);
}

// ---------------------------------------------------------------------------
// Split-fp16 HMMA GEMM, cp.async + ldmatrix, 3 CTAs/SM, ONE barrier/chunk.
// MMAs issued in three PASSES (hh over all 8 C tiles, then hl, then lh) so
// consecutive MMA issues never target the same accumulator — breaks the
// 6-deep RAW chains that pinned tensor pipe at ~32%.
//   D[M,N] = A[M,K]*B[K,N], K=256.  3 MMAs per k-step (hh+hl+lh).
// Block: 256 thr (8 warps, 4Mx2N), tile 128x64, BK=32, 2-stage ring.
// ---------------------------------------------------------------------------
#define BMg 128
#define BNg 64
#define BKg 32
#define NCH (KDIM / BKg)          // 8
#define NST 2
#define PKA 40                    // A smem pitch (halves)
#define PKB 72                    // B smem pitch (halves)
#define A_BY (BMg * PKA * 2)      // 10240
#define B_BY (BKg * PKB * 2)      // 4608
#define STG_BY (2 * A_BY + 2 * B_BY)   // 29696
#define SMEM_TOT (NST * STG_BY)        // 59392

template <int EPI>
__global__ __launch_bounds__(256, 3)
void gemm_split_kernel(const __half* __restrict__ Ahi,  // [M][K]
                       const __half* __restrict__ Alo,
                       const __half* __restrict__ Bhi,  // [batch][K][N]
                       const __half* __restrict__ Blo,
                       float* __restrict__ Cf,
                       __half* __restrict__ Chi,
                       __half* __restrict__ Clo,
                       int M, int Nfull,
                       const float* __restrict__ bias,
                       const float* __restrict__ gamma,
                       const float* __restrict__ beta,
                       const float* __restrict__ mean,
                       const float* __restrict__ var,
                       const float* __restrict__ prelu_a)
{
    extern __shared__ __align__(16) char smem[];
    const uint32_t sbase = smem_u32(smem);

    const int tid  = threadIdx.x;
    const int lane = tid & 31;
    const int wid  = tid >> 5;
    const int wm   = wid & 3;            // M warp 0..3 (32 rows each)
    const int wn   = wid >> 2;           // N warp 0..1 (32 cols each)
    const int lane15 = lane & 15;
    const int hi8    = (lane & 16) >> 1; // 0 or 8
    const int g    = lane >> 2;
    const int t2   = (lane & 3) * 2;

    const int rowBase = blockIdx.x * BMg;
    const int colBase = blockIdx.y * BNg;
    const int batch   = blockIdx.z;
    const __half* BhiP = Bhi + (size_t)batch * KDIM * Nfull;
    const __half* BloP = Blo + (size_t)batch * KDIM * Nfull;

    // cp.async indices
    const int a_idx0 = tid;              // A chunk 0 of 2
    const int a_idx1 = tid + 256;        // A chunk 1 of 2
    const int b_kr = tid >> 3;           // 0..31
    const int b_nq = tid & 7;            // 16B chunk along n

    auto issue = [&](int ch, int s) {
        const int kc = ch * BKg;
        const uint32_t stg = sbase + s * STG_BY;
#pragma unroll
        for (int i = 0; i < 2; i++) {
            const int idx = i ? a_idx1 : a_idx0;
            const int row = idx >> 2;
            const int kq  = idx & 3;
            const int gm  = rowBase + row;
            const uint32_t sz = (gm < M) ? 16u : 0u;
            const int gmc = (gm < M) ? gm : 0;
            const uint32_t adst = stg + row * (PKA * 2) + kq * 16;
            const size_t  asrc = (size_t)gmc * KDIM + kc + kq * 8;
            CP_ASYNC16(adst,        Ahi + asrc, sz);
            CP_ASYNC16(adst + A_BY, Alo + asrc, sz);
        }
        const uint32_t bdst = stg + 2 * A_BY + b_kr * (PKB * 2) + b_nq * 16;
        const size_t  bsrc = (size_t)(kc + b_kr) * Nfull + colBase + b_nq * 8;
        CP_ASYNC16(bdst,        BhiP + bsrc, 16u);
        CP_ASYNC16(bdst + B_BY, BloP + bsrc, 16u);
        CP_COMMIT();
    };

    float acc[2][4][4];
#pragma unroll
    for (int mt = 0; mt < 2; mt++)
#pragma unroll
        for (int nt = 0; nt < 4; nt++)
#pragma unroll
            for (int i = 0; i < 4; i++) acc[mt][nt][i] = 0.f;

    // prologue: 1 chunk in flight
    issue(0, 0);

    for (int c = 0; c < NCH; c++) {
        asm volatile("cp.async.wait_group 0;");
        __syncthreads();                       // stage c ready; prev compute drained
        if (c + 1 < NCH) issue(c + 1, (c + 1) % NST);  // other stage (freed last iter)

        const int s = c % NST;
        const uint32_t aHiB = sbase + s * STG_BY;
        const uint32_t aLoB = aHiB + A_BY;
        const uint32_t bHiB = aHiB + 2 * A_BY;
        const uint32_t bLoB = bHiB + B_BY;

#pragma unroll
        for (int ks = 0; ks < 2; ks++) {
            const int k0 = ks * 16;
            uint32_t ah[2][4], al[2][4], bh[2][4], bl[2][4];
#pragma unroll
            for (int mt = 0; mt < 2; mt++) {
                int row = wm * 32 + mt * 16 + lane15;
                uint32_t off = row * (PKA * 2) + (k0 + hi8) * 2;
                LDSM4(ah[mt], aHiB + off);
                LDSM4(al[mt], aLoB + off);
            }
#pragma unroll
            for (int nb = 0; nb < 2; nb++) {
                int nn   = wn * 32 + nb * 16 + hi8;
                int krow = k0 + lane15;
                uint32_t off = krow * (PKB * 2) + nn * 2;
                LDSM4T(bh[nb], bHiB + off);
                LDSM4T(bl[nb], bLoB + off);
            }
            // ---- pass 1: hi*hi — 8 MMAs, all to DIFFERENT accumulators ----
#pragma unroll
            for (int nb = 0; nb < 2; nb++)
#pragma unroll
                for (int ng = 0; ng < 2; ng++)
#pragma unroll
                    for (int mt = 0; mt < 2; mt++)
                        MMA16816(acc[mt][nb * 2 + ng], ah[mt],
                                 bh[nb][2 * ng], bh[nb][2 * ng + 1]);
            // ---- pass 2: hi*lo ----
#pragma unroll
            for (int nb = 0; nb < 2; nb++)
#pragma unroll
                for (int ng = 0; ng < 2; ng++)
#pragma unroll
                    for (int mt = 0; mt < 2; mt++)
                        MMA16816(acc[mt][nb * 2 + ng], ah[mt],
                                 bl[nb][2 * ng], bl[nb][2 * ng + 1]);
            // ---- pass 3: lo*hi ----
#pragma unroll
            for (int nb = 0; nb < 2; nb++)
#pragma unroll
                for (int ng = 0; ng < 2; ng++)
#pragma unroll
                    for (int mt = 0; mt < 2; mt++)
                        MMA16816(acc[mt][nb * 2 + ng], al[mt],
                                 bh[nb][2 * ng], bh[nb][2 * ng + 1]);
        }
    }

    // ---- epilogue (N always in-bounds: 3136 % 64 == 0) ----
#pragma unroll
    for (int mt = 0; mt < 2; mt++) {
        int r0 = rowBase + wm * 32 + mt * 16 + g;
#pragma unroll
        for (int half_ = 0; half_ < 2; half_++) {
            int rr = r0 + half_ * 8;
            if (rr >= M) continue;
            float bb = bias[rr];
            float sc = 0.f, mn = 0.f, bt = 0.f, aa = 0.f;
            if (EPI == 1) {
                sc = gamma[rr] * rsqrtf(var[rr] + EPSc);
                mn = mean[rr];
                bt = beta[rr];
                aa = prelu_a[0];
            }
#pragma unroll
            for (int nt = 0; nt < 4; nt++) {
                int col = colBase + wn * 32 + nt * 8 + t2;
                float v0 = acc[mt][nt][half_ * 2 + 0] + bb;
                float v1 = acc[mt][nt][half_ * 2 + 1] + bb;
                if (EPI == 1) {
                    v0 = (v0 - mn) * sc + bt;
                    v1 = (v1 - mn) * sc + bt;
                    v0 = v0 > 0.f ? v0 : aa * v0;
                    v1 = v1 > 0.f ? v1 : aa * v1;
                    uint32_t hw_, lw_;
                    split2(v0, v1, hw_, lw_);
                    size_t idx = ((size_t)batch * M + rr) * Nfull + col;
                    *(uint32_t*)(Chi + idx) = hw_;
                    *(uint32_t*)(Clo + idx) = lw_;
                } else {
                    size_t idx = ((size_t)batch * M + rr) * Nfull + col;
                    *(float2*)(Cf + idx) = make_float2(v0, v1);
                }
            }
        }
    }
}

// ---------------------------------------------------------------------------
// Involution aggregation — ONE barrier per block (R7 version, kept).
// ---------------------------------------------------------------------------
#define TH 4
#define HALO_R (TH + 6)           // 10
#define HALO_C 62
#define HALO_P 64                 // smem pitch

__global__ __launch_bounds__(256)
void involution_kernel(const float* __restrict__ x,
                       const float* __restrict__ ker,
                       float* __restrict__ out)
{
    __shared__ float xs[CG][HALO_R][HALO_P];   // 40 KB

    const int tileRow = blockIdx.x;
    const int g = blockIdx.y;
    const int b = blockIdx.z;
    const int tid = threadIdx.x;

    const int h0 = tileRow * TH;
    const bool active = tid < TH * Wc;          // 224
    const int r  = tid / Wc;
    const int cw = tid % Wc;
    const int h  = h0 + r;

    float kreg[KK];
    if (active) {
        const float* kp = ker + (((size_t)b * GK + g * KK) * HW) + h * Wc + cw;
#pragma unroll
        for (int idx = 0; idx < KK; idx++) kreg[idx] = kp[(size_t)idx * HW];
    }

    const float* xg = x + ((size_t)b * Cc + g * CG) * HW;
    for (int i = tid; i < CG * HALO_R * HALO_C; i += 256) {
        int ch  = i / (HALO_R * HALO_C);
        int rem = i - ch * (HALO_R * HALO_C);
        int rr  = rem / HALO_C;
        int cc  = rem - rr * HALO_C;
        int gh  = h0 - 3 + rr;
        int gw  = cc - 3;
        float v = 0.f;
        if (gh >= 0 && gh < Hc && gw >= 0 && gw < Wc)
            v = xg[(size_t)ch * HW + gh * Wc + gw];
        xs[ch][rr][cc] = v;
    }
    __syncthreads();

    if (active) {
        float* op = out + (((size_t)b * Cc + g * CG) * Hc + h) * Wc + cw;
#pragma unroll 4
        for (int ci = 0; ci < CG; ci++) {
            float a = 0.f;
#pragma unroll
            for (int i = 0; i < Kc; i++)
#pragma unroll
                for (int j = 0; j < Kc; j++)
                    a += xs[ci][r + i][cw + j] * kreg[i * Kc + j];
            op[(size_t)ci * HW] = a;
        }
    }
}

// ---------------------------------------------------------------------------
// Launch
// ---------------------------------------------------------------------------
extern "C" void kernel_launch(void* const* d_in, const int* in_sizes, int n_in,
                              void* d_out, int out_size)
{
    const float* x        = (const float*)d_in[0];
    const float* reduce_w = (const float*)d_in[1];
    const float* reduce_b = (const float*)d_in[2];
    const float* bn_gamma = (const float*)d_in[3];
    const float* bn_beta  = (const float*)d_in[4];
    const float* bn_mean  = (const float*)d_in[5];
    const float* bn_var   = (const float*)d_in[6];
    const float* prelu_a  = (const float*)d_in[7];
    const float* span_w   = (const float*)d_in[8];
    const float* span_b   = (const float*)d_in[9];
    float* out = (float*)d_out;

    __half *xh, *xl, *th, *tl, *w1h, *w1l, *w2h, *w2l;
    float* ker_buf;
    cudaGetSymbolAddress((void**)&xh, g_xh);
    cudaGetSymbolAddress((void**)&xl, g_xl);
    cudaGetSymbolAddress((void**)&th, g_th);
    cudaGetSymbolAddress((void**)&tl, g_tl);
    cudaGetSymbolAddress((void**)&w1h, g_w1h);
    cudaGetSymbolAddress((void**)&w1l, g_w1l);
    cudaGetSymbolAddress((void**)&w2h, g_w2h);
    cudaGetSymbolAddress((void**)&w2l, g_w2l);
    cudaGetSymbolAddress((void**)&ker_buf, g_ker);

    cudaFuncSetAttribute(gemm_split_kernel<1>,
                         cudaFuncAttributeMaxDynamicSharedMemorySize, SMEM_TOT);
    cudaFuncSetAttribute(gemm_split_kernel<2>,
                         cudaFuncAttributeMaxDynamicSharedMemorySize, SMEM_TOT);

    // 0) pre-split inputs
    {
        int n4 = Bc * Cc * HW / 4;
        split_kernel<<<(n4 + 255) / 256, 256>>>((const float4*)x,
                                                (uint2*)xh, (uint2*)xl, n4);
    }
    {
        int n4 = TNUM * Cc / 4;
        split_kernel<<<(n4 + 255) / 256, 256>>>((const float4*)reduce_w,
                                                (uint2*)w1h, (uint2*)w1l, n4);
    }
    {
        int n4 = GK * KDIM / 4;
        split_kernel<<<(n4 + 255) / 256, 256>>>((const float4*)span_w,
                                                (uint2*)w2h, (uint2*)w2l, n4);
    }

    // 1) GEMM1: T = BN_PReLU(reduce_w @ x), split output (feeds GEMM2)
    {
        dim3 grid(TNUM / BMg, HW / BNg, Bc);           // 2 x 49 x 4
        gemm_split_kernel<1><<<grid, 256, SMEM_TOT>>>(
            w1h, w1l, xh, xl,
            nullptr, th, tl,
            TNUM, HW,
            reduce_b, bn_gamma, bn_beta, bn_mean, bn_var, prelu_a);
    }
    // 2) GEMM2: KER = span_w @ T + span_b (fp32 out)
    {
        dim3 grid((GK + BMg - 1) / BMg, HW / BNg, Bc); // 7 x 49 x 4
        gemm_split_kernel<2><<<grid, 256, SMEM_TOT>>>(
            w2h, w2l, th, tl,
            ker_buf, nullptr, nullptr,
            GK, HW,
            span_b, nullptr, nullptr, nullptr, nullptr, nullptr);
    }
    // 3) involution aggregation
    {
        dim3 grid(Hc / TH, Gc, Bc);
        involution_kernel<<<grid, 256>>>(x, ker_buf, out);
    }
}